// round 5
// baseline (speedup 1.0000x reference)
#include <cuda_runtime.h>
#include <cuda_pipeline.h>
#include <math.h>

// Shapes
#define Bn 128
#define Tn 64
#define Un 256
#define Vn 48
#define Sn 192
#define CL 8
#define NG 16
#define NGRID 152
#define NTHR 256

typedef unsigned long long ull;
typedef unsigned int u32;

// ---------------- device globals ----------------
__device__ float    g_proj[(size_t)NG * CL * 8 * Tn * 128];  // [g][q][r][t][c]
__device__ float    g_embP[CL * Vn * 128];                   // [q][v][c]
__device__ float    g_wC[CL * Un * 128];                     // [q][k][c]
__device__ int      g_ts[Bn];

// ---------------- helpers ----------------
__device__ __forceinline__ ull pack2(float x, float y) {
    ull r; asm("mov.b64 %0, {%1, %2};" : "=l"(r) : "f"(x), "f"(y)); return r;
}
__device__ __forceinline__ void ffma2(ull& d, ull a, ull b) {
    asm("fma.rn.f32x2 %0, %1, %2, %0;" : "+l"(d) : "l"(a), "l"(b));
}
__device__ __forceinline__ ull add2(ull a, ull b) {
    ull r; asm("add.rn.f32x2 %0, %1, %2;" : "=l"(r) : "l"(a), "l"(b)); return r;
}
__device__ __forceinline__ float2 unpack2(ull v) {
    float2 f; asm("mov.b64 {%0, %1}, %2;" : "=f"(f.x), "=f"(f.y) : "l"(v)); return f;
}
__device__ __forceinline__ u32 smem_u32(const void* p) {
    u32 a; asm("{ .reg .u64 t; cvta.to.shared.u64 t, %1; cvt.u32.u64 %0, t; }" : "=r"(a) : "l"(p)); return a;
}
__device__ __forceinline__ void stc_v4(u32 la, int rank, float4 v) {
    u32 ra; asm("mapa.shared::cluster.u32 %0, %1, %2;" : "=r"(ra) : "r"(la), "r"(rank));
    asm volatile("st.shared::cluster.v4.f32 [%0], {%1, %2, %3, %4};"
                 :: "r"(ra), "f"(v.x), "f"(v.y), "f"(v.z), "f"(v.w));
}
__device__ __forceinline__ void stc_f32(u32 la, int rank, float v) {
    u32 ra; asm("mapa.shared::cluster.u32 %0, %1, %2;" : "=r"(ra) : "r"(la), "r"(rank));
    asm volatile("st.shared::cluster.f32 [%0], %1;" :: "r"(ra), "f"(v));
}
__device__ __forceinline__ void stc_u32(u32 la, int rank, u32 v) {
    u32 ra; asm("mapa.shared::cluster.u32 %0, %1, %2;" : "=r"(ra) : "r"(la), "r"(rank));
    asm volatile("st.shared::cluster.u32 [%0], %1;" :: "r"(ra), "r"(v));
}
__device__ __forceinline__ u32 ld_vol_sh(u32 addr) {
    u32 v; asm volatile("ld.volatile.shared.u32 %0, [%1];" : "=r"(v) : "r"(addr)); return v;
}
__device__ __forceinline__ float sigm(float x) { return 1.0f / (1.0f + expf(-x)); }

// ---------------- nop (ncu launch alignment) ----------------
__global__ void k_nop() {}

// ---------------- fused prep ----------------
__global__ void k_prep(const int* __restrict__ word_ids,
                       const float* __restrict__ embed,
                       const float* __restrict__ W,
                       const float* __restrict__ bias,
                       const float* __restrict__ Uw) {
    int bi = blockIdx.x, tid = threadIdx.x;
    if (bi == 0) {
        if (tid < Bn) {
            int c = 0;
            for (int t = 0; t < Tn; t++) c += (word_ids[tid * Tn + t] != 0);
            g_ts[tid] = c;
        }
        return;
    }
    if (bi <= 192) {
        int e = bi - 1;
        int t = e >> 2;
        int col = (e & 3) * 256 + tid;
        float acc = bias[col];
        for (int k = 0; k < 256; k++)
            acc += embed[t * 256 + k] * W[k * 1024 + col];
        int unit = col & 255, gate = col >> 8;
        int q = unit >> 5, ul = unit & 31;
        g_embP[(q * Vn + t) * 128 + ul * 4 + gate] = acc;
        return;
    }
    int idx = (bi - 193) * 256 + tid;
    int q = idx >> 15, r = idx & 32767;
    int k = r >> 7, c = r & 127;
    int gate = c & 3, ul = c >> 2;
    int col = gate * 256 + 32 * q + ul;
    g_wC[idx] = Uw[k * 1024 + col];
}

// ---------------- proj GEMM ----------------
__global__ void __launch_bounds__(256) k_proj(const float* __restrict__ A,
                                              const float* __restrict__ W) {
    __shared__ __align__(16) float As[64 * 16];
    __shared__ __align__(16) float Bs[16 * 64];
    int row0 = blockIdx.y * 64, col0 = blockIdx.x * 64;
    int tid = threadIdx.x;
    int tr = tid >> 4, tc = tid & 15;
    float acc[4][4] = {};
    int lr = tid >> 2, lk = (tid & 3) * 4;
    int lkb = tid >> 4, lcb = (tid & 15) * 4;
    for (int k0 = 0; k0 < 768; k0 += 16) {
        float4 av = *(const float4*)&A[(size_t)(row0 + lr) * 768 + k0 + lk];
        *(float4*)&As[lr * 16 + lk] = av;
        float4 bv = *(const float4*)&W[(size_t)(256 + k0 + lkb) * 1024 + col0 + lcb];
        *(float4*)&Bs[lkb * 64 + lcb] = bv;
        __syncthreads();
#pragma unroll
        for (int kk = 0; kk < 16; kk++) {
            float a[4];
#pragma unroll
            for (int i = 0; i < 4; i++) a[i] = As[(tr * 4 + i) * 16 + kk];
            float4 b4 = *(float4*)&Bs[kk * 64 + tc * 4];
            float b[4] = {b4.x, b4.y, b4.z, b4.w};
#pragma unroll
            for (int i = 0; i < 4; i++)
#pragma unroll
                for (int cc = 0; cc < 4; cc++) acc[i][cc] += a[i] * b[cc];
        }
        __syncthreads();
    }
#pragma unroll
    for (int i = 0; i < 4; i++) {
        int row = row0 + tr * 4 + i;
        int b = row >> 6, t = row & 63;
        int g = b >> 3, rr = b & 7;
#pragma unroll
        for (int cc = 0; cc < 4; cc++) {
            int col = col0 + tc * 4 + cc;
            int unit = col & 255, gate = col >> 8;
            int q = unit >> 5, ul = unit & 31;
            g_proj[((((size_t)(g * CL + q) * 8 + rr) * Tn + t) * 128) + ul * 4 + gate] = acc[i][cc];
        }
    }
}

// ---------------- persistent cluster decode loop ----------------
// smem floats:
#define W2S_OFF  0        // 32768  packed Uw slice (ull view)
#define RAW_OFF  32768    // 4096   h exchange, 2 parities x [G 0..63][r 0..7] float4
#define ZP_OFF   36864    // 4096   z partials (ull view) [kq][r][p]
#define WOS_OFF  40960    // 1536   Wo slice [ul][v]
#define EPP_OFF  42496    // 1024   embP prefetch [r][128]
#define PPP_OFF  43520    // 1024   proj prefetch [r][128]
#define PLOG_OFF 44544    // 768    partial logits, 2 par x [q][48]
#define H2S_OFF  45312    // 256    local h, raw-format [g 0..7][r][4]
#define CST_OFF  45568    // 256    c state per (u,r) thread
#define BOS_OFF  45824    // 48
#define CTRL_OFF 45872    // 16     8 x u32 ctrl words
#define SMEMF    45888
#define SMEMB    (SMEMF * 4)

__global__ void __launch_bounds__(NTHR, 1) __cluster_dims__(CL, 1, 1)
k_loop(const float* __restrict__ Wo, const float* __restrict__ bo,
       float* __restrict__ out) {
    extern __shared__ __align__(16) float smf[];
    int tid = threadIdx.x;
    u32 q; asm("mov.u32 %0, %%cluster_ctarank;" : "=r"(q));
    int g = blockIdx.x >> 3;
    if (g >= NG) return;
    u32 smbase = smem_u32(smf);

    float* epp  = smf + EPP_OFF;
    float* ppp  = smf + PPP_OFF;
    float* WoS  = smf + WOS_OFF;
    float* h2s  = smf + H2S_OFF;
    float* cst  = smf + CST_OFF;
    float* bos  = smf + BOS_OFF;
    volatile u32* ctrlL = (volatile u32*)(smf + CTRL_OFF);
    const ull* w2u = (const ull*)(smf + W2S_OFF);
    ull* zpu = (ull*)(smf + ZP_OFF);

    // ---- init ----
    {
        const float* wsrc = g_wC + (size_t)q * 32768;
        for (int i = tid * 4; i < 32768; i += NTHR * 4)
            __pipeline_memcpy_async(&smf[W2S_OFF + i], &wsrc[i], 16);
        __pipeline_commit();
        for (int i = tid; i < 1536; i += NTHR) WoS[i] = Wo[q * 1536 + i];
        if (tid < Vn) bos[tid] = bo[tid];
        for (int i = tid; i < 4096; i += NTHR) smf[RAW_OFF + i] = 0.f;  // h(0)=0 both parities
        cst[tid] = 0.f;
        if (tid < 8) ctrlL[tid] = 1u;   // tag 0, adj 0, tgt BOS
        __pipeline_wait_prior(0);
        __syncthreads();
        asm volatile("barrier.cluster.arrive.aligned;" ::: "memory");
        asm volatile("barrier.cluster.wait.aligned;" ::: "memory");
    }

    int p = tid & 63, kq = tid >> 6;
    int rrow = tid >> 5;              // warp id -> polled row / prefetch row
    int c4 = (tid & 31) * 4;
    int pu = tid >> 3, pr = tid & 7;  // pointwise (unit-in-slice, row)
    int row = g * 8 + (int)q;
    int hai = 0, ts = 0;
    if (tid < 32) ts = g_ts[row];
    u32 ctrl_addr = smbase + CTRL_OFF * 4 + rrow * 4;
    const ull* wt = w2u + kq * 4096 + p;

    for (int s = 0; s < Sn; s++) {
        const float4* hr4 = (const float4*)(smf + RAW_OFF + (s & 1) * 2048);

        // ---- z: 128 gate-cols x 8 rows, split-k(4), undup h groups ----
        ull a0 = 0, a1 = 0, a2 = 0, a3 = 0, a4 = 0, a5 = 0, a6 = 0, a7 = 0;
#define ZGROUP(gg) do {                                                     \
            int G = kq * 16 + (gg);                                          \
            float hv[8][4];                                                  \
            _Pragma("unroll")                                                \
            for (int r = 0; r < 8; r++) {                                    \
                float4 t4 = hr4[G * 8 + r];                                  \
                hv[r][0] = t4.x; hv[r][1] = t4.y;                            \
                hv[r][2] = t4.z; hv[r][3] = t4.w;                            \
            }                                                                \
            _Pragma("unroll")                                                \
            for (int l = 0; l < 4; l++) {                                    \
                ull w = wt[((gg) * 4 + l) * 64];                             \
                ffma2(a0, pack2(hv[0][l], hv[0][l]), w);                     \
                ffma2(a1, pack2(hv[1][l], hv[1][l]), w);                     \
                ffma2(a2, pack2(hv[2][l], hv[2][l]), w);                     \
                ffma2(a3, pack2(hv[3][l], hv[3][l]), w);                     \
                ffma2(a4, pack2(hv[4][l], hv[4][l]), w);                     \
                ffma2(a5, pack2(hv[5][l], hv[5][l]), w);                     \
                ffma2(a6, pack2(hv[6][l], hv[6][l]), w);                     \
                ffma2(a7, pack2(hv[7][l], hv[7][l]), w);                     \
            }                                                                \
        } while (0)
#pragma unroll
        for (int gg = 0; gg < 8; gg++) ZGROUP(gg);
        // mid-loop: spin on LOCAL ctrl word + prefetch ep/pp
        {
            u32 w;
            do { w = ld_vol_sh(ctrl_addr); } while ((int)(w >> 12) < s);
            int tgt = (int)(w & 63u), adjv = (int)((w >> 6) & 63u);
            __pipeline_memcpy_async(&epp[rrow * 128 + c4],
                                    &g_embP[((int)q * Vn + tgt) * 128 + c4], 16);
            __pipeline_memcpy_async(&ppp[rrow * 128 + c4],
                &g_proj[((((size_t)(g * CL + (int)q) * 8 + rrow) * Tn + adjv) * 128) + c4], 16);
            __pipeline_commit();
        }
#pragma unroll
        for (int gg = 8; gg < 16; gg++) ZGROUP(gg);
#undef ZGROUP
        __pipeline_wait_prior(0);
        {
            ull* zd = zpu + kq * 512 + p;
            zd[0 * 64] = a0; zd[1 * 64] = a1; zd[2 * 64] = a2; zd[3 * 64] = a3;
            zd[4 * 64] = a4; zd[5 * 64] = a5; zd[6 * 64] = a6; zd[7 * 64] = a7;
        }
        __syncthreads();

        // ---- pointwise (unit-in-slice pu, row pr) ----
        {
            ulonglong2 k0 = *(const ulonglong2*)(zpu + 0 * 512 + pr * 64 + 2 * pu);
            ulonglong2 k1 = *(const ulonglong2*)(zpu + 1 * 512 + pr * 64 + 2 * pu);
            ulonglong2 k2 = *(const ulonglong2*)(zpu + 2 * 512 + pr * 64 + 2 * pu);
            ulonglong2 k3 = *(const ulonglong2*)(zpu + 3 * 512 + pr * 64 + 2 * pu);
            ull s0 = add2(add2(k0.x, k1.x), add2(k2.x, k3.x));
            ull s1 = add2(add2(k0.y, k1.y), add2(k2.y, k3.y));
            float4 ep = *(const float4*)&epp[pr * 128 + 4 * pu];
            float4 pq = *(const float4*)&ppp[pr * 128 + 4 * pu];
            float2 zif = unpack2(s0);
            float2 zgo = unpack2(s1);
            float zi = zif.x + ep.x + pq.x;
            float zf = zif.y + ep.y + pq.y;
            float zg = zgo.x + ep.z + pq.z;
            float zo = zgo.y + ep.w + pq.w;
            float cold = cst[tid];
            float c2 = sigm(zf) * cold + sigm(zi) * tanhf(zg);
            float h2v = sigm(zo) * tanhf(c2);
            cst[tid] = c2;
            h2s[(pu >> 2) * 32 + pr * 4 + (pu & 3)] = h2v;   // raw format [g][r][4]
        }
        __syncthreads();

        // ---- pushes: h (512 float4 total, 2/thread) + partial logits ----
        {
            const float4* h2s4 = (const float4*)h2s;
            u32 base_la = smbase + (RAW_OFF + (((s + 1) & 1) * 2048 + (int)q * 256)) * 4;
#pragma unroll
            for (int a = tid; a < 512; a += NTHR) {
                int rank = a >> 6, jj = a & 63;
                stc_v4(base_la + jj * 16, rank, h2s4[jj]);
            }
            int v = tid & 63, rr2 = tid >> 6;
            if (v < Vn) {
                float pa0 = 0.f, pa1 = 0.f;
#pragma unroll 8
                for (int ul = 0; ul < 32; ul++) {
                    float wv = WoS[ul * Vn + v];
                    int ho = (ul >> 2) * 32 + (ul & 3);
                    pa0 += h2s[ho + rr2 * 4] * wv;
                    pa1 += h2s[ho + (rr2 + 4) * 4] * wv;
                }
                u32 pa = smbase + (PLOG_OFF + (s & 1) * 384 + (int)q * Vn + v) * 4;
                stc_f32(pa, rr2, pa0);
                stc_f32(pa, rr2 + 4, pa1);
            }
        }
        asm volatile("barrier.cluster.arrive.aligned;" ::: "memory");
        asm volatile("barrier.cluster.wait.aligned;" ::: "memory");

        // ---- owner reduce + argmax + ctrl publish (row g*8+q) ----
        {
            const float* plogB = smf + PLOG_OFF + (s & 1) * 384;
            float* fsm = epp;   // reuse (consumed this step)
            if (tid < Vn) {
                float sum = bos[tid];
#pragma unroll
                for (int qq = 0; qq < CL; qq++) sum += plogB[qq * Vn + tid];
                fsm[tid] = sum;
            }
            __syncthreads();
            if (tid < 32) {
                float bv = fsm[tid]; int bi = tid;
                if (tid < 16) {
                    float x2 = fsm[tid + 32];
                    if (x2 > bv) { bv = x2; bi = tid + 32; }
                }
#pragma unroll
                for (int off = 16; off; off >>= 1) {
                    float ov = __shfl_xor_sync(0xffffffffu, bv, off);
                    int   oi = __shfl_xor_sync(0xffffffffu, bi, off);
                    if (ov > bv || (ov == bv && oi < bi)) { bv = ov; bi = oi; }
                }
                int preds = bi;
                int res = (hai == ts) ? 0 : preds;
                if (tid == 0) out[row * Sn + s] = (float)res;
                int inc = (preds == 2 && hai < ts) ? 1 : 0;
                hai += inc;
                int adjn = (hai < ts) ? hai : hai - 1;
                u32 word = ((u32)(s + 1) << 12) | ((u32)adjn << 6) | (u32)preds;
                if (tid < 8) stc_u32(smbase + CTRL_OFF * 4 + (int)q * 4, tid, word);
            }
            __syncthreads();
        }
    }
}

// ---------------- launch ----------------
extern "C" void kernel_launch(void* const* d_in, const int* in_sizes, int n_in,
                              void* d_out, int out_size) {
    (void)in_sizes; (void)n_in; (void)out_size;
    const float* inputs   = (const float*)d_in[0];
    const int*   word_ids = (const int*)d_in[1];
    const float* embed    = (const float*)d_in[2];
    const float* W        = (const float*)d_in[3];
    const float* Uw       = (const float*)d_in[4];
    const float* bias     = (const float*)d_in[5];
    const float* Wo       = (const float*)d_in[6];
    const float* bo       = (const float*)d_in[7];
    float* out = (float*)d_out;

    static int attr_done = 0;
    if (!attr_done) {
        cudaFuncSetAttribute(k_loop, cudaFuncAttributeMaxDynamicSharedMemorySize, SMEMB);
        attr_done = 1;
    }
    k_nop<<<1, 32>>>();
    k_prep<<<1217, 256>>>(word_ids, embed, W, bias, Uw);
    k_proj<<<dim3(16, 128), 256>>>(inputs, W);
    k_loop<<<NGRID, NTHR, SMEMB>>>(Wo, bo, out);
}

// round 6
// speedup vs baseline: 1.3186x; 1.3186x over previous
#include <cuda_runtime.h>
#include <cuda_pipeline.h>
#include <math.h>

// Shapes
#define Bn 128
#define Tn 64
#define Un 256
#define Vn 48
#define Sn 192
#define CL 8
#define NG 16
#define NGRID 152
#define NTHR 256

typedef unsigned long long ull;
typedef unsigned int u32;

// ---------------- device globals ----------------
__device__ float    g_proj[(size_t)NG * CL * 8 * Tn * 128];  // [g][q][r][t][c]
__device__ float    g_embP[CL * Vn * 128];                   // [q][v][c]
__device__ float    g_wC[CL * Un * 128];                     // [q][k][c]
__device__ int      g_ts[Bn];

// ---------------- helpers ----------------
__device__ __forceinline__ ull pack2(float x, float y) {
    ull r; asm("mov.b64 %0, {%1, %2};" : "=l"(r) : "f"(x), "f"(y)); return r;
}
__device__ __forceinline__ void ffma2(ull& d, ull a, ull b) {
    asm("fma.rn.f32x2 %0, %1, %2, %0;" : "+l"(d) : "l"(a), "l"(b));
}
__device__ __forceinline__ ull add2(ull a, ull b) {
    ull r; asm("add.rn.f32x2 %0, %1, %2;" : "=l"(r) : "l"(a), "l"(b)); return r;
}
__device__ __forceinline__ float2 unpack2(ull v) {
    float2 f; asm("mov.b64 {%0, %1}, %2;" : "=f"(f.x), "=f"(f.y) : "l"(v)); return f;
}
__device__ __forceinline__ u32 smem_u32(const void* p) {
    u32 a; asm("{ .reg .u64 t; cvta.to.shared.u64 t, %1; cvt.u32.u64 %0, t; }" : "=r"(a) : "l"(p)); return a;
}
__device__ __forceinline__ void stc_u64(u32 la, int rank, ull v) {
    u32 ra; asm("mapa.shared::cluster.u32 %0, %1, %2;" : "=r"(ra) : "r"(la), "r"(rank));
    asm volatile("st.shared::cluster.u64 [%0], %1;" :: "r"(ra), "l"(v));
}
__device__ __forceinline__ void stc_f32(u32 la, int rank, float v) {
    u32 ra; asm("mapa.shared::cluster.u32 %0, %1, %2;" : "=r"(ra) : "r"(la), "r"(rank));
    asm volatile("st.shared::cluster.f32 [%0], %1;" :: "r"(ra), "f"(v));
}
__device__ __forceinline__ void stc_u32(u32 la, int rank, u32 v) {
    u32 ra; asm("mapa.shared::cluster.u32 %0, %1, %2;" : "=r"(ra) : "r"(la), "r"(rank));
    asm volatile("st.shared::cluster.u32 [%0], %1;" :: "r"(ra), "r"(v));
}
__device__ __forceinline__ u32 ld_vol_sh(u32 addr) {
    u32 v; asm volatile("ld.volatile.shared.u32 %0, [%1];" : "=r"(v) : "r"(addr)); return v;
}
__device__ __forceinline__ float sigm(float x) { return 1.0f / (1.0f + expf(-x)); }

// ---------------- nop (ncu launch alignment) ----------------
__global__ void k_nop() {}

// ---------------- fused prep ----------------
__global__ void k_prep(const int* __restrict__ word_ids,
                       const float* __restrict__ embed,
                       const float* __restrict__ W,
                       const float* __restrict__ bias,
                       const float* __restrict__ Uw) {
    int bi = blockIdx.x, tid = threadIdx.x;
    if (bi == 0) {
        if (tid < Bn) {
            int c = 0;
            for (int t = 0; t < Tn; t++) c += (word_ids[tid * Tn + t] != 0);
            g_ts[tid] = c;
        }
        return;
    }
    if (bi <= 192) {
        int e = bi - 1;
        int t = e >> 2;
        int col = (e & 3) * 256 + tid;
        float acc = bias[col];
        for (int k = 0; k < 256; k++)
            acc += embed[t * 256 + k] * W[k * 1024 + col];
        int unit = col & 255, gate = col >> 8;
        int q = unit >> 5, ul = unit & 31;
        g_embP[(q * Vn + t) * 128 + ul * 4 + gate] = acc;
        return;
    }
    int idx = (bi - 193) * 256 + tid;
    int q = idx >> 15, r = idx & 32767;
    int k = r >> 7, c = r & 127;
    int gate = c & 3, ul = c >> 2;
    int col = gate * 256 + 32 * q + ul;
    g_wC[idx] = Uw[k * 1024 + col];
}

// ---------------- proj GEMM: 128x128 tile, f32x2, cp.async double buffer ----------------
// A[8192,768] @ W[256:1024, 0:1024] -> g_proj (packed cluster layout)
__global__ void __launch_bounds__(256) k_proj(const float* __restrict__ A,
                                              const float* __restrict__ W) {
    __shared__ __align__(16) float As[2][128 * 16];
    __shared__ __align__(16) float Bs[2][16 * 128];
    int row0 = blockIdx.y * 128, col0 = blockIdx.x * 128;
    int tid = threadIdx.x;
    int tr = tid >> 4, tc = tid & 15;           // 16x16 thread grid; 8 rows x 8 cols each
    // loaders
    int lr = tid >> 1, lk = (tid & 1) * 8;      // A: 2 float4 per thread
    int lkb = tid >> 4, lcb = (tid & 15) * 8;   // B: 2 float4 per thread

    ull acc[8][4];
#pragma unroll
    for (int i = 0; i < 8; i++)
#pragma unroll
        for (int j = 0; j < 4; j++) acc[i][j] = 0ull;

    auto stage = [&](int ks) {
        int buf = ks & 1;
        int k0 = ks * 16;
        __pipeline_memcpy_async(&As[buf][lr * 16 + lk],
                                &A[(size_t)(row0 + lr) * 768 + k0 + lk], 16);
        __pipeline_memcpy_async(&As[buf][lr * 16 + lk + 4],
                                &A[(size_t)(row0 + lr) * 768 + k0 + lk + 4], 16);
        __pipeline_memcpy_async(&Bs[buf][lkb * 128 + lcb],
                                &W[(size_t)(256 + k0 + lkb) * 1024 + col0 + lcb], 16);
        __pipeline_memcpy_async(&Bs[buf][lkb * 128 + lcb + 4],
                                &W[(size_t)(256 + k0 + lkb) * 1024 + col0 + lcb + 4], 16);
        __pipeline_commit();
    };

    stage(0);
    for (int ks = 0; ks < 48; ks++) {
        if (ks < 47) { stage(ks + 1); __pipeline_wait_prior(1); }
        else         { __pipeline_wait_prior(0); }
        __syncthreads();
        int buf = ks & 1;
        const float* Ab = &As[buf][tr * 8 * 16];
        const ull*   Bb = (const ull*)&Bs[buf][tc * 8];
#pragma unroll
        for (int kk = 0; kk < 16; kk++) {
            ulonglong2 b01 = *(const ulonglong2*)(Bb + (size_t)kk * 64);
            ulonglong2 b23 = *(const ulonglong2*)(Bb + (size_t)kk * 64 + 2);
            ull bv[4] = {b01.x, b01.y, b23.x, b23.y};
#pragma unroll
            for (int i = 0; i < 8; i++) {
                float a = Ab[i * 16 + kk];
                ull ap = pack2(a, a);
                ffma2(acc[i][0], ap, bv[0]);
                ffma2(acc[i][1], ap, bv[1]);
                ffma2(acc[i][2], ap, bv[2]);
                ffma2(acc[i][3], ap, bv[3]);
            }
        }
        __syncthreads();
    }

#pragma unroll
    for (int i = 0; i < 8; i++) {
        int row = row0 + tr * 8 + i;
        int b = row >> 6, t = row & 63;
        int g = b >> 3, rr = b & 7;
#pragma unroll
        for (int j = 0; j < 4; j++) {
            float2 v = unpack2(acc[i][j]);
            int col = col0 + tc * 8 + 2 * j;
#pragma unroll
            for (int e = 0; e < 2; e++) {
                int cc = col + e;
                int unit = cc & 255, gate = cc >> 8;
                int q = unit >> 5, ul = unit & 31;
                g_proj[((((size_t)(g * CL + q) * 8 + rr) * Tn + t) * 128) + ul * 4 + gate] =
                    (e == 0) ? v.x : v.y;
            }
        }
    }
}

// ---------------- persistent cluster decode loop (reverted to 2319us version) ----------------
#define W2S_OFF  0
#define HD_OFF   32768
#define ZP_OFF   40960
#define WOS_OFF  45056
#define EPP_OFF  46592
#define PPP_OFF  47616
#define PLOG_OFF 48640
#define H2S_OFF  49408
#define CST_OFF  49664
#define BOS_OFF  49920
#define CTRL_OFF 49968
#define SMEMF    49984
#define SMEMB    (SMEMF * 4)

__global__ void __launch_bounds__(NTHR, 1) __cluster_dims__(CL, 1, 1)
k_loop(const float* __restrict__ Wo, const float* __restrict__ bo,
       float* __restrict__ out) {
    extern __shared__ __align__(16) float smf[];
    int tid = threadIdx.x;
    u32 q; asm("mov.u32 %0, %%cluster_ctarank;" : "=r"(q));
    int g = blockIdx.x >> 3;
    if (g >= NG) return;
    u32 smbase = smem_u32(smf);

    float* epp  = smf + EPP_OFF;
    float* ppp  = smf + PPP_OFF;
    float* WoS  = smf + WOS_OFF;
    float* h2s  = smf + H2S_OFF;
    float* cst  = smf + CST_OFF;
    float* bos  = smf + BOS_OFF;
    volatile u32* ctrlL = (volatile u32*)(smf + CTRL_OFF);
    const ull* w2u = (const ull*)(smf + W2S_OFF);
    ull* hdA = (ull*)(smf + HD_OFF);
    ull* zpu = (ull*)(smf + ZP_OFF);

    // ---- init ----
    {
        const float* wsrc = g_wC + (size_t)q * 32768;
        for (int i = tid * 4; i < 32768; i += NTHR * 4)
            __pipeline_memcpy_async(&smf[W2S_OFF + i], &wsrc[i], 16);
        __pipeline_commit();
        for (int i = tid; i < 1536; i += NTHR) WoS[i] = Wo[q * 1536 + i];
        if (tid < Vn) bos[tid] = bo[tid];
        for (int i = tid; i < 2048; i += NTHR) hdA[i] = 0ull;
        cst[tid] = 0.f;
        if (tid < 8) ctrlL[tid] = 1u;   // tag 0, adj 0, tgt BOS
        __pipeline_wait_prior(0);
        __syncthreads();
        asm volatile("barrier.cluster.arrive.aligned;" ::: "memory");
        asm volatile("barrier.cluster.wait.aligned;" ::: "memory");
    }

    int p = tid & 63, kq = tid >> 6;
    int rrow = tid >> 5;
    int c4 = (tid & 31) * 4;
    int pu = tid >> 3, pr = tid & 7;
    int row = g * 8 + (int)q;
    int hai = 0, ts = 0;
    if (tid < 32) ts = g_ts[row];
    u32 ctrl_addr = smbase + CTRL_OFF * 4 + rrow * 4;

    for (int s = 0; s < Sn; s++) {
        // ---- z: 128 gate-cols x 8 rows, split-k(4) ----
        const ull* wt = w2u + kq * 4096 + p;
        const ulonglong2* hp = (const ulonglong2*)(hdA + (s & 1) * 2048 + kq * 512);
        ull a0 = 0, a1 = 0, a2 = 0, a3 = 0, a4 = 0, a5 = 0, a6 = 0, a7 = 0;
#pragma unroll 8
        for (int kk = 0; kk < 32; kk++) {
            ull w = wt[kk * 64];
            ulonglong2 h01 = hp[kk * 4 + 0], h23 = hp[kk * 4 + 1];
            ulonglong2 h45 = hp[kk * 4 + 2], h67 = hp[kk * 4 + 3];
            ffma2(a0, h01.x, w); ffma2(a1, h01.y, w);
            ffma2(a2, h23.x, w); ffma2(a3, h23.y, w);
            ffma2(a4, h45.x, w); ffma2(a5, h45.y, w);
            ffma2(a6, h67.x, w); ffma2(a7, h67.y, w);
        }
        // mid-loop: spin on LOCAL smem ctrl word + prefetch ep/pp
        {
            u32 w;
            do { w = ld_vol_sh(ctrl_addr); } while ((int)(w >> 12) < s);
            int tgt = (int)(w & 63u), adjv = (int)((w >> 6) & 63u);
            __pipeline_memcpy_async(&epp[rrow * 128 + c4],
                                    &g_embP[((int)q * Vn + tgt) * 128 + c4], 16);
            __pipeline_memcpy_async(&ppp[rrow * 128 + c4],
                &g_proj[((((size_t)(g * CL + (int)q) * 8 + rrow) * Tn + adjv) * 128) + c4], 16);
            __pipeline_commit();
        }
#pragma unroll 8
        for (int kk = 32; kk < 64; kk++) {
            ull w = wt[kk * 64];
            ulonglong2 h01 = hp[kk * 4 + 0], h23 = hp[kk * 4 + 1];
            ulonglong2 h45 = hp[kk * 4 + 2], h67 = hp[kk * 4 + 3];
            ffma2(a0, h01.x, w); ffma2(a1, h01.y, w);
            ffma2(a2, h23.x, w); ffma2(a3, h23.y, w);
            ffma2(a4, h45.x, w); ffma2(a5, h45.y, w);
            ffma2(a6, h67.x, w); ffma2(a7, h67.y, w);
        }
        __pipeline_wait_prior(0);
        {
            ull* zd = zpu + kq * 512 + p;
            zd[0 * 64] = a0; zd[1 * 64] = a1; zd[2 * 64] = a2; zd[3 * 64] = a3;
            zd[4 * 64] = a4; zd[5 * 64] = a5; zd[6 * 64] = a6; zd[7 * 64] = a7;
        }
        __syncthreads();

        // ---- pointwise (unit-in-slice pu, row pr) ----
        {
            ulonglong2 k0 = *(const ulonglong2*)(zpu + 0 * 512 + pr * 64 + 2 * pu);
            ulonglong2 k1 = *(const ulonglong2*)(zpu + 1 * 512 + pr * 64 + 2 * pu);
            ulonglong2 k2 = *(const ulonglong2*)(zpu + 2 * 512 + pr * 64 + 2 * pu);
            ulonglong2 k3 = *(const ulonglong2*)(zpu + 3 * 512 + pr * 64 + 2 * pu);
            ull s0 = add2(add2(k0.x, k1.x), add2(k2.x, k3.x));
            ull s1 = add2(add2(k0.y, k1.y), add2(k2.y, k3.y));
            float4 ep = *(const float4*)&epp[pr * 128 + 4 * pu];
            float4 pq = *(const float4*)&ppp[pr * 128 + 4 * pu];
            float2 zif = unpack2(s0);
            float2 zgo = unpack2(s1);
            float zi = zif.x + ep.x + pq.x;
            float zf = zif.y + ep.y + pq.y;
            float zg = zgo.x + ep.z + pq.z;
            float zo = zgo.y + ep.w + pq.w;
            float cold = cst[tid];
            float c2 = sigm(zf) * cold + sigm(zi) * tanhf(zg);
            float h2v = sigm(zo) * tanhf(c2);
            cst[tid] = c2;
            h2s[pu * 8 + pr] = h2v;
            ull hh = pack2(h2v, h2v);
            u32 la = smbase + HD_OFF * 4 +
                     ((((s + 1) & 1) * 2048 + (32 * (int)q + pu) * 8 + pr) * 8);
#pragma unroll
            for (int d = 0; d < CL; d++) stc_u64(la, d, hh);
        }
        __syncthreads();

        // ---- partial logits for own 32-unit slice -> push to row owners ----
        {
            int v = tid & 63, rr2 = tid >> 6;
            if (v < Vn) {
                float pa0 = 0.f, pa1 = 0.f;
#pragma unroll 8
                for (int ul = 0; ul < 32; ul++) {
                    float wv = WoS[ul * Vn + v];
                    pa0 += h2s[ul * 8 + rr2] * wv;
                    pa1 += h2s[ul * 8 + rr2 + 4] * wv;
                }
                u32 pa = smbase + PLOG_OFF * 4 + (((s & 1) * 384 + (int)q * Vn + v) * 4);
                stc_f32(pa, rr2, pa0);
                stc_f32(pa, rr2 + 4, pa1);
            }
        }
        asm volatile("barrier.cluster.arrive.aligned;" ::: "memory");
        asm volatile("barrier.cluster.wait.aligned;" ::: "memory");

        // ---- owner reduce + argmax + DSMEM ctrl publish ----
        {
            const float* plogB = smf + PLOG_OFF + (s & 1) * 384;
            float* fsm = epp;
            if (tid < Vn) {
                float sum = bos[tid];
#pragma unroll
                for (int qq = 0; qq < CL; qq++) sum += plogB[qq * Vn + tid];
                fsm[tid] = sum;
            }
            __syncthreads();
            if (tid < 32) {
                float bv = fsm[tid]; int bi = tid;
                if (tid < 16) {
                    float x2 = fsm[tid + 32];
                    if (x2 > bv) { bv = x2; bi = tid + 32; }
                }
#pragma unroll
                for (int off = 16; off; off >>= 1) {
                    float ov = __shfl_xor_sync(0xffffffffu, bv, off);
                    int   oi = __shfl_xor_sync(0xffffffffu, bi, off);
                    if (ov > bv || (ov == bv && oi < bi)) { bv = ov; bi = oi; }
                }
                int preds = bi;
                int res = (hai == ts) ? 0 : preds;
                if (tid == 0) out[row * Sn + s] = (float)res;
                int inc = (preds == 2 && hai < ts) ? 1 : 0;
                hai += inc;
                int adjn = (hai < ts) ? hai : hai - 1;
                u32 word = ((u32)(s + 1) << 12) | ((u32)adjn << 6) | (u32)preds;
                if (tid < 8) stc_u32(smbase + CTRL_OFF * 4 + (int)q * 4, tid, word);
            }
            __syncthreads();
        }
    }
}

// ---------------- launch ----------------
extern "C" void kernel_launch(void* const* d_in, const int* in_sizes, int n_in,
                              void* d_out, int out_size) {
    (void)in_sizes; (void)n_in; (void)out_size;
    const float* inputs   = (const float*)d_in[0];
    const int*   word_ids = (const int*)d_in[1];
    const float* embed    = (const float*)d_in[2];
    const float* W        = (const float*)d_in[3];
    const float* Uw       = (const float*)d_in[4];
    const float* bias     = (const float*)d_in[5];
    const float* Wo       = (const float*)d_in[6];
    const float* bo       = (const float*)d_in[7];
    float* out = (float*)d_out;

    static int attr_done = 0;
    if (!attr_done) {
        cudaFuncSetAttribute(k_loop, cudaFuncAttributeMaxDynamicSharedMemorySize, SMEMB);
        attr_done = 1;
    }
    k_nop<<<1, 32>>>();
    k_prep<<<1217, 256>>>(word_ids, embed, W, bias, Uw);
    k_proj<<<dim3(8, 64), 256>>>(inputs, W);
    k_loop<<<NGRID, NTHR, SMEMB>>>(Wo, bo, out);
}